// round 2
// baseline (speedup 1.0000x reference)
#include <cuda_runtime.h>

// SSIM loss: pred/target fp32 (8,8,3,256,256) -> scalar 1 - mean(ssim_map)
// 192 planes of 256x256. Depthwise 11x11 Gaussian (sigma=1.5), separable.

#define HW       256
#define PLANE    (HW * HW)
#define NPLANES  192
#define TILES_X  8
#define TILES_Y  8
#define NBLOCKS  (TILES_X * TILES_Y * NPLANES)   // 12288
#define NTHREADS 256
#define NPIX     12582912.0                       // 192*256*256

__device__ float        g_partials[NBLOCKS];
__device__ unsigned int g_ticket = 0;            // reset to 0 by last block (replay-safe)

// Normalized Gaussian weights for ws=11, sigma=1.5.
#define GW0 0.00102838f
#define GW1 0.00759872f
#define GW2 0.03600084f
#define GW3 0.10936034f
#define GW4 0.21300566f
#define GW5 0.26601220f

typedef unsigned long long ull;

__device__ __forceinline__ void fma2(ull& d, ull a, ull b) {
    asm("fma.rn.f32x2 %0, %1, %2, %0;" : "+l"(d) : "l"(a), "l"(b));
}
__device__ __forceinline__ ull pack2(float lo, float hi) {
    ull r;
    asm("mov.b64 %0, {%1, %2};" : "=l"(r) : "f"(lo), "f"(hi));
    return r;
}

__global__ __launch_bounds__(NTHREADS) void ssim_main(
    const float* __restrict__ pred, const float* __restrict__ targ,
    float* __restrict__ out)
{
    // Horizontal-conv intermediates: 42 rows (32 out + 2*5 halo) x 32 cols, 5 quantities
    __shared__ float s_int[5][42 * 32];   // 26880 B
    // Vertical results: 32x32, 5 quantities
    __shared__ float s_fin[5][32 * 32];   // 20480 B
    __shared__ float s_red[8];
    __shared__ int   s_last;

    const int tid = threadIdx.x;
    const int ox = blockIdx.x * 32;
    const int oy = blockIdx.y * 32;
    const int plane = blockIdx.z;
    const float* __restrict__ px = pred + (size_t)plane * PLANE;
    const float* __restrict__ py = targ + (size_t)plane * PLANE;

    const float W[11] = {GW0, GW1, GW2, GW3, GW4, GW5, GW4, GW3, GW2, GW1, GW0};

    // ---- Phase A: fused global load + products + horizontal conv ----
    // Tasks: 42 rows x 8 col-groups (4 outputs each) = 336
    for (int task = tid; task < 42 * 8; task += NTHREADS) {
        const int r  = task >> 3;
        const int c0 = (task & 7) * 4;
        const int gy = oy + r - 5;

        if ((unsigned)gy >= (unsigned)HW) {
            const float4 z = make_float4(0.f, 0.f, 0.f, 0.f);
            #pragma unroll
            for (int q = 0; q < 5; q++)
                *reinterpret_cast<float4*>(&s_int[q][r * 32 + c0]) = z;
        } else {
            const float* __restrict__ rx = px + gy * HW;
            const float* __restrict__ ry = py + gy * HW;
            const int gx0 = ox + c0 - 5;

            float xv[14], yv[14];
            if (gx0 >= 0 && gx0 + 13 < HW) {
                // interior fast path: no bounds predication
                #pragma unroll
                for (int i = 0; i < 14; i++) {
                    xv[i] = __ldg(rx + gx0 + i);
                    yv[i] = __ldg(ry + gx0 + i);
                }
            } else {
                #pragma unroll
                for (int i = 0; i < 14; i++) {
                    const int gx = gx0 + i;
                    const bool ok = (unsigned)gx < (unsigned)HW;
                    xv[i] = ok ? __ldg(rx + gx) : 0.0f;
                    yv[i] = ok ? __ldg(ry + gx) : 0.0f;
                }
            }

            // q0: x
            {
                float a0 = 0.f, a1 = 0.f, a2 = 0.f, a3 = 0.f;
                #pragma unroll
                for (int k = 0; k < 11; k++) {
                    a0 = fmaf(W[k], xv[k],     a0);
                    a1 = fmaf(W[k], xv[k + 1], a1);
                    a2 = fmaf(W[k], xv[k + 2], a2);
                    a3 = fmaf(W[k], xv[k + 3], a3);
                }
                *reinterpret_cast<float4*>(&s_int[0][r * 32 + c0]) = make_float4(a0, a1, a2, a3);
            }
            // q1: y
            {
                float a0 = 0.f, a1 = 0.f, a2 = 0.f, a3 = 0.f;
                #pragma unroll
                for (int k = 0; k < 11; k++) {
                    a0 = fmaf(W[k], yv[k],     a0);
                    a1 = fmaf(W[k], yv[k + 1], a1);
                    a2 = fmaf(W[k], yv[k + 2], a2);
                    a3 = fmaf(W[k], yv[k + 3], a3);
                }
                *reinterpret_cast<float4*>(&s_int[1][r * 32 + c0]) = make_float4(a0, a1, a2, a3);
            }
            // q2: x*x
            float v[14];
            #pragma unroll
            for (int i = 0; i < 14; i++) v[i] = xv[i] * xv[i];
            {
                float a0 = 0.f, a1 = 0.f, a2 = 0.f, a3 = 0.f;
                #pragma unroll
                for (int k = 0; k < 11; k++) {
                    a0 = fmaf(W[k], v[k],     a0);
                    a1 = fmaf(W[k], v[k + 1], a1);
                    a2 = fmaf(W[k], v[k + 2], a2);
                    a3 = fmaf(W[k], v[k + 3], a3);
                }
                *reinterpret_cast<float4*>(&s_int[2][r * 32 + c0]) = make_float4(a0, a1, a2, a3);
            }
            // q3: y*y
            #pragma unroll
            for (int i = 0; i < 14; i++) v[i] = yv[i] * yv[i];
            {
                float a0 = 0.f, a1 = 0.f, a2 = 0.f, a3 = 0.f;
                #pragma unroll
                for (int k = 0; k < 11; k++) {
                    a0 = fmaf(W[k], v[k],     a0);
                    a1 = fmaf(W[k], v[k + 1], a1);
                    a2 = fmaf(W[k], v[k + 2], a2);
                    a3 = fmaf(W[k], v[k + 3], a3);
                }
                *reinterpret_cast<float4*>(&s_int[3][r * 32 + c0]) = make_float4(a0, a1, a2, a3);
            }
            // q4: x*y
            #pragma unroll
            for (int i = 0; i < 14; i++) v[i] = xv[i] * yv[i];
            {
                float a0 = 0.f, a1 = 0.f, a2 = 0.f, a3 = 0.f;
                #pragma unroll
                for (int k = 0; k < 11; k++) {
                    a0 = fmaf(W[k], v[k],     a0);
                    a1 = fmaf(W[k], v[k + 1], a1);
                    a2 = fmaf(W[k], v[k + 2], a2);
                    a3 = fmaf(W[k], v[k + 3], a3);
                }
                *reinterpret_cast<float4*>(&s_int[4][r * 32 + c0]) = make_float4(a0, a1, a2, a3);
            }
        }
    }
    __syncthreads();

    // ---- Phase B: vertical conv, f32x2-packed (2 columns/instruction) ----
    // Tasks: 5 quantities x 4 row-groups (8 rows) x 16 col-pairs = 320
    {
        ull WW[6];
        WW[0] = pack2(GW0, GW0); WW[1] = pack2(GW1, GW1); WW[2] = pack2(GW2, GW2);
        WW[3] = pack2(GW3, GW3); WW[4] = pack2(GW4, GW4); WW[5] = pack2(GW5, GW5);

        for (int task = tid; task < 320; task += NTHREADS) {
            const int q   = task >> 6;          // 0..4
            const int rem = task & 63;
            const int rg  = rem >> 4;           // 0..3
            const int cp  = rem & 15;           // col pair 0..15
            const int r0  = rg * 8;
            const int cc  = cp * 2;

            ull v[18];
            #pragma unroll
            for (int k = 0; k < 18; k++)
                v[k] = *reinterpret_cast<const ull*>(&s_int[q][(r0 + k) * 32 + cc]);

            #pragma unroll
            for (int j = 0; j < 8; j++) {
                ull a = 0ULL;  // (+0.0f, +0.0f)
                #pragma unroll
                for (int k = 0; k < 11; k++) {
                    const int wi = (k < 6) ? k : 10 - k;
                    fma2(a, v[j + k], WW[wi]);
                }
                *reinterpret_cast<ull*>(&s_fin[q][(r0 + j) * 32 + cc]) = a;
            }
        }
    }
    __syncthreads();

    // ---- Phase C: SSIM map + block reduction ----
    float lsum = 0.0f;
    #pragma unroll
    for (int i = 0; i < 4; i++) {
        const int idx = tid + i * NTHREADS;
        const float mx = s_fin[0][idx];
        const float my = s_fin[1][idx];
        const float xx = s_fin[2][idx];
        const float yy = s_fin[3][idx];
        const float xy = s_fin[4][idx];

        const float mx2 = mx * mx;
        const float my2 = my * my;
        const float mxy = mx * my;
        const float sx  = fmaxf(xx - mx2, 0.0f);
        const float sy  = fmaxf(yy - my2, 0.0f);
        const float sxy = xy - mxy;

        const float num = (2.0f * mxy + 1e-4f) * (2.0f * sxy + 9e-4f);
        const float den = (mx2 + my2 + 1e-4f) * (sx + sy + 9e-4f);
        float s = num / (den + 1e-8f);
        if (!isfinite(s)) s = 0.0f;
        lsum += s;
    }

    #pragma unroll
    for (int o = 16; o > 0; o >>= 1)
        lsum += __shfl_down_sync(0xffffffffu, lsum, o);
    if ((tid & 31) == 0) s_red[tid >> 5] = lsum;
    __syncthreads();

    if (tid == 0) {
        float v = 0.0f;
        #pragma unroll
        for (int w = 0; w < 8; w++) v += s_red[w];
        const int bid = (blockIdx.z * TILES_Y + blockIdx.y) * TILES_X + blockIdx.x;
        g_partials[bid] = v;
        __threadfence();
        const unsigned t = atomicAdd(&g_ticket, 1u);
        s_last = (t == NBLOCKS - 1);
    }
    __syncthreads();

    // ---- Last block: deterministic final reduction (fixed order) ----
    if (s_last) {
        __shared__ double sr[NTHREADS];
        double s = 0.0;
        for (int i = tid; i < NBLOCKS; i += NTHREADS)
            s += (double)g_partials[i];
        sr[tid] = s;
        __syncthreads();
        for (int off = NTHREADS / 2; off > 0; off >>= 1) {
            if (tid < off) sr[tid] += sr[tid + off];
            __syncthreads();
        }
        if (tid == 0) {
            out[0] = 1.0f - (float)(sr[0] / NPIX);
            g_ticket = 0;   // reset for next graph replay
        }
    }
}

extern "C" void kernel_launch(void* const* d_in, const int* in_sizes, int n_in,
                              void* d_out, int out_size)
{
    const float* pred = (const float*)d_in[0];
    const float* targ = (const float*)d_in[1];
    dim3 grid(TILES_X, TILES_Y, NPLANES);
    ssim_main<<<grid, NTHREADS>>>(pred, targ, (float*)d_out);
}